// round 15
// baseline (speedup 1.0000x reference)
#include <cuda_runtime.h>
#include <math.h>

#define NBITS   20
#define NSUB    ((1u << NBITS) - 1u)    // 1048575 elements in w
#define NT32    (1 << (NBITS - 5))      // 32768 threads, 32 elements each
#define NBLK    256
#define NTPB    128
#define NWARP   (NTPB / 32)
#define FULLM   0xFFFFFFFFu

// Single pass: per-element dot with the per-subset coefficient, decomposed as
// c_i = c_low5(i & 31) + c_high(i >> 5). Coefficient tables built in smem by
// warp 0 while every thread's 8 LDG.128 are in flight. One atomicAdd per
// block into the memset-zeroed output.
__global__ void __launch_bounds__(NTPB) mil_main_kernel(const float* __restrict__ w,
                                                        const float* __restrict__ yprob,
                                                        const int*   __restrict__ Yp,
                                                        int has_Y,
                                                        float* __restrict__ out) {
    const int tid  = threadIdx.x;
    const int warp = tid >> 5;
    const int lane = tid & 31;
    const int t    = blockIdx.x * NTPB + tid;   // chunk id, 0..32767 (exact cover)
    const int e0   = t << 5;                    // first element index of this chunk

    // ---- issue all 8 LDG.128 first; full-array MLP, hides coefficient setup ----
    float v[32];
    const float4* __restrict__ w4 = (const float4*)w;
    if (t != NT32 - 1) {
#pragma unroll
        for (int g = 0; g < 8; g++) {
            float4 a = w4[(e0 >> 2) + g];
            v[4*g+0]=a.x; v[4*g+1]=a.y; v[4*g+2]=a.z; v[4*g+3]=a.w;
        }
    } else {
        // last chunk: e = 1048544..1048574 exist; e = 1048575 does not
#pragma unroll
        for (int g = 0; g < 7; g++) {
            float4 a = w4[(e0 >> 2) + g];
            v[4*g+0]=a.x; v[4*g+1]=a.y; v[4*g+2]=a.z; v[4*g+3]=a.w;
        }
        v[28] = w[e0 + 28];
        v[29] = w[e0 + 29];
        v[30] = w[e0 + 30];
        v[31] = 0.0f;                    // subset index 2^20 does not exist
    }

    // ---- warp 0 builds cf[0..20] and the low-5-bit table cl5[32] in smem ----
    // cf[b] (b<20) = coeff of bit b of subset idx = logp[19-b] - log1mp[19-b]
    // cf[20]       = sum_j log1mp[j]  (constant term of every c_i)
    __shared__ float cf[NBITS + 1];
    __shared__ float cl5[32];
    __shared__ float sp[NWARP];
    const int y_nonzero = has_Y ? (Yp[0] != 0) : 1;
    float base = 0.0f;                           // valid on warp 0 after reduce
    if (warp == 0) {
        const float pp  = (lane < NBITS) ? yprob[lane] : 0.5f;
        const float lpv = logf(pp);
        const float l1v = logf(1.0f - pp);
        const float diff = lpv - l1v;
        float b1 = (lane < NBITS) ? l1v : 0.0f;
#pragma unroll
        for (int o = 16; o > 0; o >>= 1) b1 += __shfl_xor_sync(FULLM, b1, o);
        base = b1;                               // sum of log1mp
        const int   src   = (lane < NBITS) ? (NBITS - 1 - lane) : 0;
        const float cdiff = __shfl_sync(FULLM, diff, src);
        float cv;
        if      (lane <  NBITS) cv = cdiff;
        else if (lane == NBITS) cv = base;
        else                    cv = 0.0f;
        if (!y_nonzero)         cv = 0.0f;       // Y==0: closed form added by block 0
        if (lane <= NBITS) cf[lane] = cv;

        const float c0 = __shfl_sync(FULLM, cv, 0);
        const float c1 = __shfl_sync(FULLM, cv, 1);
        const float c2 = __shfl_sync(FULLM, cv, 2);
        const float c3 = __shfl_sync(FULLM, cv, 3);
        const float c4 = __shfl_sync(FULLM, cv, 4);
        float s5 = 0.0f;
        if (lane & 1)  s5 += c0;
        if (lane & 2)  s5 += c1;
        if (lane & 4)  s5 += c2;
        if (lane & 8)  s5 += c3;
        if (lane & 16) s5 += c4;
        cl5[lane] = s5;
    }
    __syncthreads();

    // ---- c_high for this chunk (bits >=5 of i = bits of t, 15 bits) and for
    //      the boundary element (bits of t+1). t+1 == 2^15 only when v[31]==0,
    //      so dropping bit 15 is harmless. ----
    const unsigned ut  = (unsigned)t;
    const unsigned ut1 = ut + 1u;
    float ch  = cf[NBITS];
    float ch2 = cf[NBITS];
#pragma unroll
    for (int b = 0; b < 15; b++) {
        const float c = cf[5 + b];
        if ((ut  >> b) & 1u) ch  += c;
        if ((ut1 >> b) & 1u) ch2 += c;
    }

    // ---- per-element dot: k=0..30 -> low5 = k+1; element 31 -> low5 = 0 ----
    float a0 = 0.0f, a1 = 0.0f, a2 = 0.0f, a3 = 0.0f;
#pragma unroll
    for (int k = 0; k < 28; k += 4) {
        a0 = fmaf(v[k+0], cl5[k+1], a0);
        a1 = fmaf(v[k+1], cl5[k+2], a1);
        a2 = fmaf(v[k+2], cl5[k+3], a2);
        a3 = fmaf(v[k+3], cl5[k+4], a3);
    }
    a0 = fmaf(v[28], cl5[29], a0);
    a1 = fmaf(v[29], cl5[30], a1);
    a2 = fmaf(v[30], cl5[31], a2);

    // S31 = sum of v[0..30], clean pairwise tree (no shared subterms)
    float T1[16];
#pragma unroll
    for (int k = 0; k < 15; k++) T1[k] = v[2*k] + v[2*k+1];
    T1[15] = v[30];
    float T2[8];
#pragma unroll
    for (int k = 0; k < 8; k++) T2[k] = T1[2*k] + T1[2*k+1];
    const float S31 = ((T2[0] + T2[1]) + (T2[2] + T2[3]))
                    + ((T2[4] + T2[5]) + (T2[6] + T2[7]));

    float acc = ((a0 + a1) + (a2 + a3)) + ch * S31 + ch2 * v[31];

    // ---- warp reduce, block fold, one atomic per block ----
#pragma unroll
    for (int o = 16; o > 0; o >>= 1) acc += __shfl_xor_sync(FULLM, acc, o);
    if (lane == 0) sp[warp] = acc;
    __syncthreads();
    if (tid == 0) {
        float a = (sp[0] + sp[1]) + (sp[2] + sp[3]);
        if (!y_nonzero && blockIdx.x == 0)
            a += (float)((double)NSUB * (double)base);
        atomicAdd(out, a);
    }
}

extern "C" void kernel_launch(void* const* d_in, const int* in_sizes, int n_in,
                              void* d_out, int out_size) {
    const float* yprob = (const float*)d_in[0];
    const float* w     = (const float*)d_in[1];
    const int*   Yp    = (n_in >= 3) ? (const int*)d_in[2] : nullptr;
    float*       out   = (float*)d_out;
    (void)in_sizes; (void)out_size;

    cudaMemsetAsync(out, 0, sizeof(float));   // graph-capturable memset node
    mil_main_kernel<<<NBLK, NTPB>>>(w, yprob, Yp, Yp != nullptr ? 1 : 0, out);
}

// round 16
// speedup vs baseline: 1.0464x; 1.0464x over previous
#include <cuda_runtime.h>
#include <math.h>

#define NBITS   20
#define NSUB    ((1u << NBITS) - 1u)    // 1048575 elements in w
#define NT16    (1 << (NBITS - 4))      // 65536 threads, 16 elements each
#define NBLK    512
#define NTPB    128
#define NWARP   (NTPB / 32)
#define FULLM   0xFFFFFFFFu

// Cross-block scalar accumulator + arrival counter; both reset by the final
// block each launch -> deterministic across graph replays. Single graph node.
__device__ float        g_acc   = 0.0f;
__device__ unsigned int g_count = 0;

__global__ void __launch_bounds__(NTPB) mil_main_kernel(const float* __restrict__ w,
                                                        const float* __restrict__ yprob,
                                                        const int*   __restrict__ Yp,
                                                        int has_Y,
                                                        float* __restrict__ out) {
    const int tid  = threadIdx.x;
    const int warp = tid >> 5;
    const int lane = tid & 31;
    const int t    = blockIdx.x * NTPB + tid;   // chunk id, 0..65535 (exact cover)
    const int e0   = t << 4;                    // first element index of this chunk

    // ---- issue all 4 LDG.128 first; latency hides the coefficient setup ----
    float v[16];
    const float4* __restrict__ w4 = (const float4*)w;
    if (t != NT16 - 1) {
#pragma unroll
        for (int g = 0; g < 4; g++) {
            float4 a = w4[(e0 >> 2) + g];
            v[4*g+0]=a.x; v[4*g+1]=a.y; v[4*g+2]=a.z; v[4*g+3]=a.w;
        }
    } else {
#pragma unroll
        for (int g = 0; g < 3; g++) {
            float4 a = w4[(e0 >> 2) + g];
            v[4*g+0]=a.x; v[4*g+1]=a.y; v[4*g+2]=a.z; v[4*g+3]=a.w;
        }
        v[12] = w[e0 + 12];
        v[13] = w[e0 + 13];
        v[14] = w[e0 + 14];
        v[15] = 0.0f;                    // subset index 2^20 does not exist
    }

    // ---- warp 0 builds cf[0..20] and the low-4-bit table cl4[16] in smem ----
    // cf[b] (b<20) = coeff of bit b of subset idx = logp[19-b] - log1mp[19-b]
    // cf[20]       = sum_j log1mp[j]  (constant term of every c_i)
    __shared__ float cf[NBITS + 1];
    __shared__ float cl4[16];
    __shared__ float sp[NWARP];
    const int y_nonzero = has_Y ? (Yp[0] != 0) : 1;
    float base = 0.0f;                           // valid on warp 0 after reduce
    if (warp == 0) {
        const float pp  = (lane < NBITS) ? yprob[lane] : 0.5f;
        const float lpv = logf(pp);
        const float l1v = logf(1.0f - pp);
        const float diff = lpv - l1v;
        float b1 = (lane < NBITS) ? l1v : 0.0f;
#pragma unroll
        for (int o = 16; o > 0; o >>= 1) b1 += __shfl_xor_sync(FULLM, b1, o);
        base = b1;                               // sum of log1mp
        const int   src   = (lane < NBITS) ? (NBITS - 1 - lane) : 0;
        const float cdiff = __shfl_sync(FULLM, diff, src);
        float cv;
        if      (lane <  NBITS) cv = cdiff;
        else if (lane == NBITS) cv = base;
        else                    cv = 0.0f;
        if (!y_nonzero)         cv = 0.0f;       // Y==0: closed form added by block 0
        if (lane <= NBITS) cf[lane] = cv;

        const float c0 = __shfl_sync(FULLM, cv, 0);
        const float c1 = __shfl_sync(FULLM, cv, 1);
        const float c2 = __shfl_sync(FULLM, cv, 2);
        const float c3 = __shfl_sync(FULLM, cv, 3);
        if (lane < 16) {
            float s = 0.0f;
            if (lane & 1) s += c0;
            if (lane & 2) s += c1;
            if (lane & 4) s += c2;
            if (lane & 8) s += c3;
            cl4[lane] = s;
        }
    }
    __syncthreads();

    // ---- c_high for this chunk (bits >=4 of i = bits of t, 16 bits) and for
    //      the boundary element (bits of t+1). t+1 == 2^16 only when v[15]==0,
    //      so dropping bit 16 is harmless. ----
    const unsigned ut  = (unsigned)t;
    const unsigned ut1 = ut + 1u;
    float ch  = cf[NBITS];
    float ch2 = cf[NBITS];
#pragma unroll
    for (int b = 0; b < 16; b++) {
        const float c = cf[4 + b];
        if ((ut  >> b) & 1u) ch  += c;
        if ((ut1 >> b) & 1u) ch2 += c;
    }

    // ---- per-element dot: k=0..14 -> low4 = k+1; element 15 -> low4 = 0 ----
    float a0 = 0.0f, a1 = 0.0f, a2 = 0.0f, a3 = 0.0f;
#pragma unroll
    for (int k = 0; k < 12; k += 4) {
        a0 = fmaf(v[k+0], cl4[k+1], a0);
        a1 = fmaf(v[k+1], cl4[k+2], a1);
        a2 = fmaf(v[k+2], cl4[k+3], a2);
        a3 = fmaf(v[k+3], cl4[k+4], a3);
    }
    a0 = fmaf(v[12], cl4[13], a0);
    a1 = fmaf(v[13], cl4[14], a1);
    a2 = fmaf(v[14], cl4[15], a2);

    // S15 = sum of v[0..14], clean pairwise tree
    const float s01 = v[0] + v[1],  s23 = v[2] + v[3];
    const float s45 = v[4] + v[5],  s67 = v[6] + v[7];
    const float s89 = v[8] + v[9],  sAB = v[10] + v[11];
    const float sCD = v[12] + v[13];
    const float S15 = ((s01 + s23) + (s45 + s67)) + ((s89 + sAB) + (sCD + v[14]));

    float acc = ((a0 + a1) + (a2 + a3)) + ch * S15 + ch2 * v[15];

    // ---- warp reduce, block fold ----
#pragma unroll
    for (int o = 16; o > 0; o >>= 1) acc += __shfl_xor_sync(FULLM, acc, o);
    if (lane == 0) sp[warp] = acc;
    __syncthreads();

    // ---- featherweight single-thread tail: no extra syncs, other warps retire ----
    if (tid == 0) {
        float a = (sp[0] + sp[1]) + (sp[2] + sp[3]);
        if (!y_nonzero && blockIdx.x == 0)
            a += (float)((double)NSUB * (double)base);   // Y==0 closed form
        atomicAdd(&g_acc, a);
        __threadfence();                    // publish g_acc before the ticket
        const unsigned ticket = atomicAdd(&g_count, 1u);
        if (ticket == NBLK - 1) {
            __threadfence();                // all 512 g_acc adds visible
            const float r = atomicAdd(&g_acc, 0.0f);   // coherent read
            out[0] = r;                     // single full write (poison-safe)
            g_acc   = 0.0f;                 // reset for next graph replay
            g_count = 0u;
        }
    }
}

extern "C" void kernel_launch(void* const* d_in, const int* in_sizes, int n_in,
                              void* d_out, int out_size) {
    const float* yprob = (const float*)d_in[0];
    const float* w     = (const float*)d_in[1];
    const int*   Yp    = (n_in >= 3) ? (const int*)d_in[2] : nullptr;
    float*       out   = (float*)d_out;
    (void)in_sizes; (void)out_size;

    mil_main_kernel<<<NBLK, NTPB>>>(w, yprob, Yp, Yp != nullptr ? 1 : 0, out);
}

// round 17
// speedup vs baseline: 1.1401x; 1.0895x over previous
#include <cuda_runtime.h>
#include <math.h>

#define NBITS   20
#define NSUB    ((1u << NBITS) - 1u)    // 1048575 elements in w
#define NT16    (1 << (NBITS - 4))      // 65536 threads, 16 elements each
#define NBLK    512
#define NTPB    128
#define NWARP   (NTPB / 32)
#define FULLM   0xFFFFFFFFu

// Single pass: per-element dot with the per-subset coefficient, decomposed as
// c_i = c_low4(i & 15) + c_high(i >> 4). Coefficients built in smem by warp 0
// while every thread's 4 LDG.128 are in flight. One atomicAdd per block into
// the memset-zeroed output. (Best measured config: 8.13 us, rel_err 7.3e-5.)
__global__ void __launch_bounds__(NTPB) mil_main_kernel(const float* __restrict__ w,
                                                        const float* __restrict__ yprob,
                                                        const int*   __restrict__ Yp,
                                                        int has_Y,
                                                        float* __restrict__ out) {
    const int tid  = threadIdx.x;
    const int warp = tid >> 5;
    const int lane = tid & 31;
    const int t    = blockIdx.x * NTPB + tid;   // chunk id, 0..65535 (exact cover)
    const int e0   = t << 4;                    // first element index of this chunk

    // ---- issue all 4 LDG.128 first; latency hides the coefficient setup ----
    float v[16];
    const float4* __restrict__ w4 = (const float4*)w;
    if (t != NT16 - 1) {
#pragma unroll
        for (int g = 0; g < 4; g++) {
            float4 a = w4[(e0 >> 2) + g];
            v[4*g+0]=a.x; v[4*g+1]=a.y; v[4*g+2]=a.z; v[4*g+3]=a.w;
        }
    } else {
#pragma unroll
        for (int g = 0; g < 3; g++) {
            float4 a = w4[(e0 >> 2) + g];
            v[4*g+0]=a.x; v[4*g+1]=a.y; v[4*g+2]=a.z; v[4*g+3]=a.w;
        }
        v[12] = w[e0 + 12];
        v[13] = w[e0 + 13];
        v[14] = w[e0 + 14];
        v[15] = 0.0f;                    // subset index 2^20 does not exist
    }

    // ---- warp 0 builds cf[0..20] and the low-4-bit table cl4[16] in smem ----
    // cf[b] (b<20) = coefficient of bit b of the subset index = logp[19-b]-log1mp[19-b]
    // cf[20]       = sum_j log1mp[j]  (constant term of every c_i)
    __shared__ float cf[NBITS + 1];
    __shared__ float cl4[16];
    __shared__ float sp[NWARP];
    const int y_nonzero = has_Y ? (Yp[0] != 0) : 1;
    float base = 0.0f;                           // valid on warp 0 after reduce
    if (warp == 0) {
        const float pp  = (lane < NBITS) ? yprob[lane] : 0.5f;
        const float lpv = logf(pp);
        const float l1v = logf(1.0f - pp);
        const float diff = lpv - l1v;
        float b1 = (lane < NBITS) ? l1v : 0.0f;
#pragma unroll
        for (int o = 16; o > 0; o >>= 1) b1 += __shfl_xor_sync(FULLM, b1, o);
        base = b1;                               // sum of log1mp
        const int   src   = (lane < NBITS) ? (NBITS - 1 - lane) : 0;
        const float cdiff = __shfl_sync(FULLM, diff, src);
        float cv;
        if      (lane <  NBITS) cv = cdiff;
        else if (lane == NBITS) cv = base;
        else                    cv = 0.0f;
        if (!y_nonzero)         cv = 0.0f;       // Y==0: closed form added by block 0
        if (lane <= NBITS) cf[lane] = cv;

        const float c0 = __shfl_sync(FULLM, cv, 0);
        const float c1 = __shfl_sync(FULLM, cv, 1);
        const float c2 = __shfl_sync(FULLM, cv, 2);
        const float c3 = __shfl_sync(FULLM, cv, 3);
        if (lane < 16) {
            float s = 0.0f;
            if (lane & 1) s += c0;
            if (lane & 2) s += c1;
            if (lane & 4) s += c2;
            if (lane & 8) s += c3;
            cl4[lane] = s;
        }
    }
    __syncthreads();

    // ---- c_high for this chunk (bits >=4 of i are the bits of t) and for the
    //      boundary element (bits of t+1). t < 2^16, so 16 bits suffice;
    //      t+1 == 2^16 only when v[15] == 0, so dropping bit 16 is harmless. ----
    const unsigned ut  = (unsigned)t;
    const unsigned ut1 = ut + 1u;
    float ch  = cf[NBITS];
    float ch2 = cf[NBITS];
#pragma unroll
    for (int b = 0; b < 16; b++) {
        const float c = cf[4 + b];
        if ((ut  >> b) & 1u) ch  += c;
        if ((ut1 >> b) & 1u) ch2 += c;
    }

    // ---- per-element dot: elements k=0..14 have low4 = k+1; element 15 has low4=0 ----
    float a0 = 0.0f, a1 = 0.0f, a2 = 0.0f, a3 = 0.0f;
#pragma unroll
    for (int k = 0; k < 12; k += 4) {
        a0 = fmaf(v[k+0], cl4[k+1], a0);
        a1 = fmaf(v[k+1], cl4[k+2], a1);
        a2 = fmaf(v[k+2], cl4[k+3], a2);
        a3 = fmaf(v[k+3], cl4[k+4], a3);
    }
    a0 = fmaf(v[12], cl4[13], a0);
    a1 = fmaf(v[13], cl4[14], a1);
    a2 = fmaf(v[14], cl4[15], a2);

    // S15 = sum of v[0..14], clean pairwise tree (no shared subterms)
    const float s01 = v[0] + v[1],  s23 = v[2] + v[3];
    const float s45 = v[4] + v[5],  s67 = v[6] + v[7];
    const float s89 = v[8] + v[9],  sAB = v[10] + v[11];
    const float sCD = v[12] + v[13];
    const float S15 = ((s01 + s23) + (s45 + s67)) + ((s89 + sAB) + (sCD + v[14]));

    float acc = ((a0 + a1) + (a2 + a3)) + ch * S15 + ch2 * v[15];

    // ---- warp reduce, block fold, one atomic per block ----
#pragma unroll
    for (int o = 16; o > 0; o >>= 1) acc += __shfl_xor_sync(FULLM, acc, o);
    if (lane == 0) sp[warp] = acc;
    __syncthreads();
    if (tid == 0) {
        float a = (sp[0] + sp[1]) + (sp[2] + sp[3]);
        if (!y_nonzero && blockIdx.x == 0)
            a += (float)((double)NSUB * (double)base);
        atomicAdd(out, a);
    }
}

extern "C" void kernel_launch(void* const* d_in, const int* in_sizes, int n_in,
                              void* d_out, int out_size) {
    const float* yprob = (const float*)d_in[0];
    const float* w     = (const float*)d_in[1];
    const int*   Yp    = (n_in >= 3) ? (const int*)d_in[2] : nullptr;
    float*       out   = (float*)d_out;
    (void)in_sizes; (void)out_size;

    cudaMemsetAsync(out, 0, sizeof(float));   // graph-capturable memset node
    mil_main_kernel<<<NBLK, NTPB>>>(w, yprob, Yp, Yp != nullptr ? 1 : 0, out);
}